// round 16
// baseline (speedup 1.0000x reference)
// R16: CSR aggregation (built once per call, used by both layers) replaces
// vector-RED scatter + zero passes; agg fuses mean=(sum+h)/(deg+1) into one
// fp16 write, so sage GEMM's A is fully cp.async (mean | h). GEMM core from R15.
#include <cuda_runtime.h>
#include <cuda_fp16.h>
#include <math.h>
#include <stdint.h>

#define NN   100000
#define NE   500000
#define FEATD 128
#define HIDD  256
#define NL   16384

// ---------------- persistent scratch ------------------------------------------
__device__ __half g_h  [(size_t)NN * HIDD];
__device__ __half g_mean[(size_t)NN * HIDD];
__device__ __half g_h2 [(size_t)NN * HIDD];
__device__ __half g_comb[(size_t)NL * 4 * HIDD];
__device__ float  g_lacc[NL];
__device__ int    g_is64;
__device__ int    g_degi[NN];
__device__ int    g_rowstart[NN + 1];
__device__ int    g_cursor[NN];
__device__ int    g_csr[NE];

__device__ __half g_wembC[HIDD*FEATD];
__device__ __half g_wl0C[HIDD*HIDD];
__device__ __half g_wr0C[HIDD*HIDD];
__device__ __half g_wl1C[HIDD*HIDD];
__device__ __half g_wr1C[HIDD*HIDD];
__device__ __half g_wp1C[HIDD*4*HIDD];

// ---------------- helpers -------------------------------------------------------
__device__ __forceinline__ uint32_t smem_u32(const void* p) {
    uint32_t a;
    asm("{ .reg .u64 t; cvta.to.shared.u64 t, %1; cvt.u32.u64 %0, t; }"
        : "=r"(a) : "l"(p));
    return a;
}
static __device__ __forceinline__ uint32_t swz(uint32_t x) {
    return x ^ ((x >> 3) & 0x70);
}
__device__ __forceinline__ long long idx_at(const void* p, long long i, int is64) {
    if (is64) return ((const long long*)p)[i];
    return (long long)((const int*)p)[i];
}
__device__ __forceinline__ void ldmx4(uint32_t* r, uint32_t a) {
    asm volatile("ldmatrix.sync.aligned.m8n8.x4.shared.b16 {%0,%1,%2,%3}, [%4];"
                 : "=r"(r[0]), "=r"(r[1]), "=r"(r[2]), "=r"(r[3]) : "r"(a));
}
__device__ __forceinline__ void cp16(uint32_t dst, const void* src) {
    asm volatile("cp.async.cg.shared.global [%0], [%1], 16;"
                 :: "r"(dst), "l"(src));
}
#define CP_COMMIT() asm volatile("cp.async.commit_group;" ::: "memory")
#define CP_WAIT0()  asm volatile("cp.async.wait_group 0;" ::: "memory")
#define MMA_F16(d, a, b) \
    asm volatile("mma.sync.aligned.m16n8k16.row.col.f32.f16.f16.f32 " \
        "{%0,%1,%2,%3}, {%4,%5,%6,%7}, {%8,%9}, {%0,%1,%2,%3};" \
        : "+f"((d)[0]), "+f"((d)[1]), "+f"((d)[2]), "+f"((d)[3]) \
        : "r"((a)[0]), "r"((a)[1]), "r"((a)[2]), "r"((a)[3]), \
          "r"((b)[0]), "r"((b)[1]))

// ---------------- prep: detect + weight conversion + per-call zeroing -----------
__global__ void prep_kernel(const void* ei,
                            const float* __restrict__ wemb,
                            const float* __restrict__ wl0, const float* __restrict__ wr0,
                            const float* __restrict__ wl1, const float* __restrict__ wr1,
                            const float* __restrict__ wp1) {
    int i = blockIdx.x * 256 + threadIdx.x;
    if (i == 0) {
        const unsigned* w = (const unsigned*)ei;
        int zeros = 0;
        for (int j = 1; j < 128; j += 2) zeros += (w[j] == 0u);
        g_is64 = (zeros >= 50) ? 1 : 0;
    }
    if (i < NN) g_degi[i] = 0;
    if (i < NL) g_lacc[i] = 0.f;
    if (i < 32768)       g_wembC[i]          = __float2half(wemb[i]);
    else if (i < 98304)  g_wl0C[i - 32768]   = __float2half(wl0[i - 32768]);
    else if (i < 163840) g_wr0C[i - 98304]   = __float2half(wr0[i - 98304]);
    else if (i < 229376) g_wl1C[i - 163840]  = __float2half(wl1[i - 163840]);
    else if (i < 294912) g_wr1C[i - 229376]  = __float2half(wr1[i - 229376]);
    else if (i < 557056) g_wp1C[i - 294912]  = __float2half(wp1[i - 294912]);
}

// ---------------- CSR build ------------------------------------------------------
__global__ void degi_kernel(const void* ei) {
    int e = blockIdx.x * blockDim.x + threadIdx.x;
    if (e < NE) {
        long long d = idx_at(ei, (long long)NE + e, g_is64);
        atomicAdd(&g_degi[d], 1);
    }
}

// one-block hierarchical exclusive scan of g_degi -> g_rowstart / g_cursor
#define SCAN_T 1024
#define CHUNK  ((NN + SCAN_T - 1) / SCAN_T)   // 98
__global__ __launch_bounds__(SCAN_T) void scan_kernel() {
    __shared__ int sm[SCAN_T];
    const int t = threadIdx.x;
    const int beg = t * CHUNK;
    const int end = min(beg + CHUNK, NN);
    int tot = 0;
    for (int i = beg; i < end; i++) tot += g_degi[i];
    sm[t] = tot;
    __syncthreads();
    for (int off = 1; off < SCAN_T; off <<= 1) {
        int v = (t >= off) ? sm[t - off] : 0;
        __syncthreads();
        sm[t] += v;
        __syncthreads();
    }
    int run = sm[t] - tot;            // exclusive offset for this thread's chunk
    for (int i = beg; i < end; i++) {
        g_rowstart[i] = run;
        g_cursor[i]   = run;
        run += g_degi[i];
    }
    if (end == NN && beg < NN) g_rowstart[NN] = run;
    if (t == SCAN_T - 1 && end <= beg) g_rowstart[NN] = sm[SCAN_T - 1];
}

__global__ void scatter_kernel(const void* ei) {
    int e = blockIdx.x * blockDim.x + threadIdx.x;
    if (e < NE) {
        int is64 = g_is64;
        long long s = idx_at(ei, e, is64);
        long long d = idx_at(ei, (long long)NE + e, is64);
        int pos = atomicAdd(&g_cursor[(int)d], 1);
        g_csr[pos] = (int)s;
    }
}

// ---------------- aggregation: warp-per-node gather, fused mean ------------------
__global__ __launch_bounds__(256) void agg_csr(const __half* __restrict__ h,
                                               __half* __restrict__ mean) {
    int n = blockIdx.x * 8 + (threadIdx.x >> 5);
    if (n >= NN) return;
    const int lane = threadIdx.x & 31;
    const int beg = g_rowstart[n], end = g_rowstart[n + 1];
    float acc[8];
    {
        uint4 sv = *(const uint4*)(h + (size_t)n * HIDD + lane * 8);
        const __half2* s2 = (const __half2*)&sv;
#pragma unroll
        for (int k = 0; k < 4; k++) {
            float2 f = __half22float2(s2[k]);
            acc[2 * k] = f.x; acc[2 * k + 1] = f.y;
        }
    }
    int j = beg;
    for (; j + 2 <= end; j += 2) {            // 2-way unroll for MLP
        int s0 = g_csr[j], s1 = g_csr[j + 1];
        uint4 v0 = *(const uint4*)(h + (size_t)s0 * HIDD + lane * 8);
        uint4 v1 = *(const uint4*)(h + (size_t)s1 * HIDD + lane * 8);
        const __half2* a2 = (const __half2*)&v0;
        const __half2* b2 = (const __half2*)&v1;
#pragma unroll
        for (int k = 0; k < 4; k++) {
            float2 fa = __half22float2(a2[k]);
            float2 fb = __half22float2(b2[k]);
            acc[2 * k]     += fa.x + fb.x;
            acc[2 * k + 1] += fa.y + fb.y;
        }
    }
    if (j < end) {
        uint4 v = *(const uint4*)(h + (size_t)g_csr[j] * HIDD + lane * 8);
        const __half2* a2 = (const __half2*)&v;
#pragma unroll
        for (int k = 0; k < 4; k++) {
            float2 f = __half22float2(a2[k]);
            acc[2 * k] += f.x; acc[2 * k + 1] += f.y;
        }
    }
    const float iv = 1.f / (float)(end - beg + 1);
    uint4 o;
    __half2* o2 = (__half2*)&o;
#pragma unroll
    for (int k = 0; k < 4; k++)
        o2[k] = __floats2half2_rn(acc[2 * k] * iv, acc[2 * k + 1] * iv);
    *(uint4*)(mean + (size_t)n * HIDD + lane * 8) = o;
}

// ---------------- link combine + finish ------------------------------------------
__global__ __launch_bounds__(256) void comb_kernel(const __half* __restrict__ h,
                                                   const void* sp, const void* dp) {
    int t = blockIdx.x * 256 + threadIdx.x;   // NL*32 total
    int l = t >> 5, q = t & 31;
    int is64 = g_is64;
    long long si = idx_at(sp, l, is64);
    long long di = idx_at(dp, l, is64);
    uint4 s4 = *(const uint4*)(h + (size_t)si * HIDD + q * 8);
    uint4 d4 = *(const uint4*)(h + (size_t)di * HIDD + q * 8);
    uint4 m4, a4;
    const __half2* s2 = (const __half2*)&s4;
    const __half2* d2 = (const __half2*)&d4;
    __half2* m2 = (__half2*)&m4;
    __half2* a2 = (__half2*)&a4;
#pragma unroll
    for (int k = 0; k < 4; k++) {
        m2[k] = __hmul2(s2[k], d2[k]);
        a2[k] = __habs2(__hsub2(s2[k], d2[k]));
    }
    __half* row = g_comb + (size_t)l * 1024;
    *(uint4*)(row + q * 8)       = s4;
    *(uint4*)(row + 256 + q * 8) = d4;
    *(uint4*)(row + 512 + q * 8) = m4;
    *(uint4*)(row + 768 + q * 8) = a4;
}

__global__ void linkfin_kernel(const float* __restrict__ bp2, float* __restrict__ out) {
    int i = blockIdx.x * 256 + threadIdx.x;
    if (i < NL) out[i] = 1.f / (1.f + expf(-(g_lacc[i] + bp2[0])));
}

// ---------------- pipelined fp16 GEMM, BM=64 BN=256, 2 CTAs/SM ------------------
// MODE 0: embed (A = x fp32, convert path)
// MODE 1: sage  (A async: mean for c<4, h for c>=4)
// MODE 2: link  (A async from comb)

#define SA_    0
#define SW_    8192
#define BUFSZ  40960          // A 8K + W 32K
#define S_MISC 81920
#define SMEMB  (S_MISC + 512 + 1024)

template <int MODE>
__global__ __launch_bounds__(256, 2) void gemm_tc(
    const float* __restrict__ Af, const __half* __restrict__ Ah,
    const __half* __restrict__ Am,
    const __half* __restrict__ W1, const __half* __restrict__ W2,
    const float* __restrict__ bias, const float* __restrict__ wp2,
    __half* __restrict__ outp)
{
    extern __shared__ char smraw[];
    char* smc = (char*)(((uintptr_t)smraw + 1023) & ~(uintptr_t)1023);
    const uint32_t sbase = smem_u32(smc);
    const int tid = threadIdx.x;
    const int wid = tid >> 5, l = tid & 31;
    const int wm = wid >> 2, wn = wid & 3;       // 2 x 4 warp grid
    const int row0 = blockIdx.x * 64;

    constexpr int NCH = (MODE == 0) ? 2 : (MODE == 1) ? 8 : 16;
    constexpr int KA  = (MODE == 0) ? FEATD : (MODE == 1) ? HIDD : 1024;

    float acc[2][8][4];
#pragma unroll
    for (int mt = 0; mt < 2; mt++)
#pragma unroll
        for (int nt = 0; nt < 8; nt++)
#pragma unroll
            for (int j = 0; j < 4; j++) acc[mt][nt][j] = 0.f;

    float4 phv[2];            // MODE 0 prefetch

    auto issueW = [&](int c, int b) {
        const __half* W = (MODE == 1 && c >= 4) ? W2 : W1;
        const int colbase = (MODE == 1) ? ((c & 3) * 64) : (c * 64);
#pragma unroll
        for (int j = 0; j < 8; j++) {            // 2048 uint4 slots
            const int id  = j * 256 + tid;
            const int r   = id >> 3, c16 = id & 7;
            cp16(sbase + b * BUFSZ + SW_ + swz(r * 128 + c16 * 16),
                 W + (size_t)r * KA + colbase + c16 * 8);
        }
    };
    auto issueA = [&](int c, int b) {
        const __half* src = (MODE == 1 && c < 4) ? Am : Ah;
        const int colbase = (MODE == 1) ? ((c & 3) * 64) : (c * 64);
#pragma unroll
        for (int j = 0; j < 2; j++) {            // 512 uint4 slots
            const int id  = j * 256 + tid;
            const int r   = id >> 3, c16 = id & 7;
            const uint32_t dst = sbase + b * BUFSZ + SA_ + swz(r * 128 + c16 * 16);
            if (MODE == 2 || row0 + r < NN)
                cp16(dst, src + (size_t)(row0 + r) * KA + colbase + c16 * 8);
            else
                *(uint4*)(smc + (dst - sbase)) = make_uint4(0u, 0u, 0u, 0u);
        }
    };
    auto loadA = [&](int c, int h) {             // MODE 0 only
        const int colbase = c * 64;
#pragma unroll
        for (int i = 0; i < 2; i++) {
            const int id = (h * 2 + i) * 256 + tid;
            const int r  = id >> 4, c4 = id & 15;
            phv[i] = make_float4(0.f, 0.f, 0.f, 0.f);
            if (row0 + r < NN)
                phv[i] = *(const float4*)(Af + (size_t)(row0 + r) * KA + colbase + c4 * 4);
        }
    };
    auto storeA = [&](int h, int b) {            // MODE 0 only
#pragma unroll
        for (int i = 0; i < 2; i++) {
            const int id = (h * 2 + i) * 256 + tid;
            const int r  = id >> 4, c4 = id & 15;
            uint2 o;
            ((__half2*)&o)[0] = __floats2half2_rn(phv[i].x, phv[i].y);
            ((__half2*)&o)[1] = __floats2half2_rn(phv[i].z, phv[i].w);
            *(uint2*)(smc + b * BUFSZ + SA_ + swz(r * 128 + c4 * 8)) = o;
        }
    };
    auto mma2 = [&](int b, int kk0) {
        const uint32_t ab = sbase + b * BUFSZ;
#pragma unroll
        for (int kk = kk0; kk < kk0 + 2; kk++) {
            const uint32_t kbyte = kk * 32;
            uint32_t ar[2][4];
#pragma unroll
            for (int mt = 0; mt < 2; mt++) {
                uint32_t off = swz((wm * 32 + mt * 16 + (l & 15)) * 128 +
                                   kbyte + ((l >> 4) << 4));
                ldmx4(ar[mt], ab + SA_ + off);
            }
            uint32_t bf[8][2];
#pragma unroll
            for (int ntb = 0; ntb < 4; ntb++) {
                const int nt2 = ntb * 2;
                uint32_t off = swz((wn * 64 + (nt2 + ((l >> 4) & 1)) * 8 + (l & 7)) * 128
                                   + kbyte + (((l >> 3) & 1) << 4));
                uint32_t r[4];
                ldmx4(r, ab + SW_ + off);
                bf[nt2][0] = r[0]; bf[nt2][1] = r[1];
                bf[nt2 + 1][0] = r[2]; bf[nt2 + 1][1] = r[3];
            }
#pragma unroll
            for (int nt = 0; nt < 8; nt++)
#pragma unroll
                for (int mt = 0; mt < 2; mt++)
                    MMA_F16(acc[mt][nt], ar[mt], bf[nt]);
        }
    };

    // ---- prologue ----
    issueW(0, 0);
    if (MODE == 0) {
        loadA(0, 0); storeA(0, 0);
        loadA(0, 1); storeA(1, 0);
    } else {
        issueA(0, 0);
    }
    CP_COMMIT();
    CP_WAIT0();
    __syncthreads();

    // ---- pipelined main loop ----
    for (int c = 0; c < NCH; c++) {
        const int b = c & 1, nb = b ^ 1;
        const bool pf = (c + 1 < NCH);
        if (pf) {
            issueW(c + 1, nb);
            if (MODE == 0) loadA(c + 1, 0); else issueA(c + 1, nb);
            CP_COMMIT();
        }
        mma2(b, 0);
        if (MODE == 0 && pf) { storeA(0, nb); loadA(c + 1, 1); }
        mma2(b, 2);
        if (MODE == 0 && pf) storeA(1, nb);
        CP_WAIT0();
        __syncthreads();
    }

    // ---- epilogue ----
    if (MODE == 2) {
#pragma unroll
        for (int mt = 0; mt < 2; mt++) {
            int rloc = wm * 32 + mt * 16 + (l >> 2);
            float s0 = 0.f, s1 = 0.f;
#pragma unroll
            for (int nt = 0; nt < 8; nt++) {
                int col = wn * 64 + nt * 8 + (l & 3) * 2;
                float b0 = bias[col], b1 = bias[col + 1];
                float w0 = wp2[col],  w1 = wp2[col + 1];
                s0 += fmaxf(acc[mt][nt][0] + b0, 0.f) * w0
                    + fmaxf(acc[mt][nt][1] + b1, 0.f) * w1;
                s1 += fmaxf(acc[mt][nt][2] + b0, 0.f) * w0
                    + fmaxf(acc[mt][nt][3] + b1, 0.f) * w1;
            }
            atomicAdd(&g_lacc[row0 + rloc], s0);
            atomicAdd(&g_lacc[row0 + rloc + 8], s1);
        }
    } else {
#pragma unroll
        for (int mt = 0; mt < 2; mt++) {
            int r0 = row0 + wm * 32 + mt * 16 + (l >> 2);
#pragma unroll
            for (int nt = 0; nt < 8; nt++) {
                int col = wn * 64 + nt * 8 + (l & 3) * 2;
                float b0 = bias[col], b1 = bias[col + 1];
                float v0 = acc[mt][nt][0] + b0, v1 = acc[mt][nt][1] + b1;
                float v2 = acc[mt][nt][2] + b0, v3 = acc[mt][nt][3] + b1;
                if (MODE == 1) {
                    v0 = fmaxf(v0, 0.f); v1 = fmaxf(v1, 0.f);
                    v2 = fmaxf(v2, 0.f); v3 = fmaxf(v3, 0.f);
                }
                if (r0 < NN)
                    *(__half2*)(outp + (size_t)r0 * HIDD + col) = __floats2half2_rn(v0, v1);
                if (r0 + 8 < NN)
                    *(__half2*)(outp + (size_t)(r0 + 8) * HIDD + col) = __floats2half2_rn(v2, v3);
            }
        }
    }
}

// ---------------- launcher ------------------------------------------------------
extern "C" void kernel_launch(void* const* d_in, const int* in_sizes, int n_in,
                              void* d_out, int out_size) {
    (void)in_sizes; (void)n_in; (void)out_size;
    const float* x     = (const float*)d_in[0];
    const void*  ei    = d_in[1];
    const void*  sidx  = d_in[3];
    const void*  didx  = d_in[4];
    const float* w_emb = (const float*)d_in[5];
    const float* b_emb = (const float*)d_in[6];
    const float* wl0 = (const float*)d_in[8];
    const float* bl0 = (const float*)d_in[9];
    const float* wr0 = (const float*)d_in[10];
    const float* wl1 = (const float*)d_in[13];
    const float* bl1 = (const float*)d_in[14];
    const float* wr1 = (const float*)d_in[15];
    const float* wp1 = (const float*)d_in[18];
    const float* bp1 = (const float*)d_in[19];
    const float* wp2 = (const float*)d_in[20];
    const float* bp2 = (const float*)d_in[21];
    float* out = (float*)d_out;

    cudaFuncSetAttribute(gemm_tc<0>, cudaFuncAttributeMaxDynamicSharedMemorySize, SMEMB);
    cudaFuncSetAttribute(gemm_tc<1>, cudaFuncAttributeMaxDynamicSharedMemorySize, SMEMB);
    cudaFuncSetAttribute(gemm_tc<2>, cudaFuncAttributeMaxDynamicSharedMemorySize, SMEMB);

    __half *wembC, *wl0C, *wr0C, *wl1C, *wr1C, *wp1C;
    __half *hbuf, *meanbuf, *h2buf, *combbuf;
    cudaGetSymbolAddress((void**)&wembC, g_wembC);
    cudaGetSymbolAddress((void**)&wl0C, g_wl0C);
    cudaGetSymbolAddress((void**)&wr0C, g_wr0C);
    cudaGetSymbolAddress((void**)&wl1C, g_wl1C);
    cudaGetSymbolAddress((void**)&wr1C, g_wr1C);
    cudaGetSymbolAddress((void**)&wp1C, g_wp1C);
    cudaGetSymbolAddress((void**)&hbuf, g_h);
    cudaGetSymbolAddress((void**)&meanbuf, g_mean);
    cudaGetSymbolAddress((void**)&h2buf, g_h2);
    cudaGetSymbolAddress((void**)&combbuf, g_comb);

    const int ggrid = (NN + 63) / 64;                // 1563
    const int lgrid = NL / 64;                       // 256
    const int agrid = (NN + 7) / 8;                  // 12500

    prep_kernel<<<(557056 + 255) / 256, 256>>>(ei, w_emb, wl0, wr0, wl1, wr1, wp1); // 0
    degi_kernel<<<(NE + 255) / 256, 256>>>(ei);                                     // 1
    scan_kernel<<<1, SCAN_T>>>();                                                   // 2
    scatter_kernel<<<(NE + 255) / 256, 256>>>(ei);                                  // 3
    gemm_tc<0><<<ggrid, 256, SMEMB>>>(x, nullptr, nullptr, wembC, nullptr,
                                      b_emb, nullptr, hbuf);                        // 4
    agg_csr<<<agrid, 256>>>(hbuf, meanbuf);                                         // 5 <- ncu
    gemm_tc<1><<<ggrid, 256, SMEMB>>>(nullptr, hbuf, meanbuf, wl0C, wr0C,
                                      bl0, nullptr, h2buf);                         // 6
    agg_csr<<<agrid, 256>>>(h2buf, meanbuf);                                        // 7
    gemm_tc<1><<<ggrid, 256, SMEMB>>>(nullptr, h2buf, meanbuf, wl1C, wr1C,
                                      bl1, nullptr, hbuf);                          // 8
    comb_kernel<<<NL * 32 / 256, 256>>>(hbuf, sidx, didx);                          // 9
    gemm_tc<2><<<lgrid, 256, SMEMB>>>(nullptr, combbuf, nullptr, wp1C, nullptr,
                                      bp1, wp2, nullptr);                           // 10
    linkfin_kernel<<<NL / 256, 256>>>(bp2, out);                                    // 11
}

// round 17
// speedup vs baseline: 1.1655x; 1.1655x over previous
// R17: revert of CSR regression — back to R15's vector-RED scatter aggregation
// and pipelined BM=64/BN=256 GEMM. Cleanup: two RED buffers zeroed in prep
// (removes both standalone zero kernels); ncu slot 5 now captures agg_kernel.
#include <cuda_runtime.h>
#include <cuda_fp16.h>
#include <math.h>
#include <stdint.h>

#define NN   100000
#define NE   500000
#define FEATD 128
#define HIDD  256
#define NL   16384

// ---------------- persistent scratch ------------------------------------------
__device__ float  g_deg[NN];
__device__ __half g_h  [(size_t)NN * HIDD];
__device__ __half g_agg [(size_t)NN * HIDD];
__device__ __half g_agg2[(size_t)NN * HIDD];
__device__ __half g_h2 [(size_t)NN * HIDD];
__device__ __half g_comb[(size_t)NL * 4 * HIDD];
__device__ float  g_lacc[NL];
__device__ int    g_is64;

__device__ __half g_wembC[HIDD*FEATD];
__device__ __half g_wl0C[HIDD*HIDD];
__device__ __half g_wr0C[HIDD*HIDD];
__device__ __half g_wl1C[HIDD*HIDD];
__device__ __half g_wr1C[HIDD*HIDD];
__device__ __half g_wp1C[HIDD*4*HIDD];

// ---------------- helpers -------------------------------------------------------
__device__ __forceinline__ uint32_t smem_u32(const void* p) {
    uint32_t a;
    asm("{ .reg .u64 t; cvta.to.shared.u64 t, %1; cvt.u32.u64 %0, t; }"
        : "=r"(a) : "l"(p));
    return a;
}
static __device__ __forceinline__ uint32_t swz(uint32_t x) {
    return x ^ ((x >> 3) & 0x70);
}
__device__ __forceinline__ long long idx_at(const void* p, long long i, int is64) {
    if (is64) return ((const long long*)p)[i];
    return (long long)((const int*)p)[i];
}
__device__ __forceinline__ void ldmx4(uint32_t* r, uint32_t a) {
    asm volatile("ldmatrix.sync.aligned.m8n8.x4.shared.b16 {%0,%1,%2,%3}, [%4];"
                 : "=r"(r[0]), "=r"(r[1]), "=r"(r[2]), "=r"(r[3]) : "r"(a));
}
__device__ __forceinline__ void cp16(uint32_t dst, const void* src) {
    asm volatile("cp.async.cg.shared.global [%0], [%1], 16;"
                 :: "r"(dst), "l"(src));
}
#define CP_COMMIT() asm volatile("cp.async.commit_group;" ::: "memory")
#define CP_WAIT0()  asm volatile("cp.async.wait_group 0;" ::: "memory")
#define MMA_F16(d, a, b) \
    asm volatile("mma.sync.aligned.m16n8k16.row.col.f32.f16.f16.f32 " \
        "{%0,%1,%2,%3}, {%4,%5,%6,%7}, {%8,%9}, {%0,%1,%2,%3};" \
        : "+f"((d)[0]), "+f"((d)[1]), "+f"((d)[2]), "+f"((d)[3]) \
        : "r"((a)[0]), "r"((a)[1]), "r"((a)[2]), "r"((a)[3]), \
          "r"((b)[0]), "r"((b)[1]))

// ---------------- prep: detect + weight conversion + zero RED buffers -----------
__global__ void prep_kernel(const void* ei,
                            const float* __restrict__ wemb,
                            const float* __restrict__ wl0, const float* __restrict__ wr0,
                            const float* __restrict__ wl1, const float* __restrict__ wr1,
                            const float* __restrict__ wp1) {
    int i = blockIdx.x * 256 + threadIdx.x;
    if (i == 0) {
        const unsigned* w = (const unsigned*)ei;
        int zeros = 0;
        for (int j = 1; j < 128; j += 2) zeros += (w[j] == 0u);
        g_is64 = (zeros >= 50) ? 1 : 0;
    }
    if (i < NN * HIDD / 8) {
        ((uint4*)g_agg)[i]  = make_uint4(0u, 0u, 0u, 0u);
        ((uint4*)g_agg2)[i] = make_uint4(0u, 0u, 0u, 0u);
    }
    if (i < NN) g_deg[i]  = 0.f;
    if (i < NL) g_lacc[i] = 0.f;
    if (i < 32768)       g_wembC[i]          = __float2half(wemb[i]);
    else if (i < 98304)  g_wl0C[i - 32768]   = __float2half(wl0[i - 32768]);
    else if (i < 163840) g_wr0C[i - 98304]   = __float2half(wr0[i - 98304]);
    else if (i < 229376) g_wl1C[i - 163840]  = __float2half(wl1[i - 163840]);
    else if (i < 294912) g_wr1C[i - 229376]  = __float2half(wr1[i - 229376]);
    else if (i < 557056) g_wp1C[i - 294912]  = __float2half(wp1[i - 294912]);
}

// ---------------- misc small kernels -------------------------------------------
__global__ void deg_kernel(const void* ei) {
    int e = blockIdx.x * blockDim.x + threadIdx.x;
    if (e < NE) {
        long long d = idx_at(ei, (long long)NE + e, g_is64);
        atomicAdd(&g_deg[d], 1.f);
    }
}

// 8 edges / block, 32 lanes per edge; 16B gather + v4.f16x2 vector RED.
__global__ __launch_bounds__(256) void agg_kernel(const __half* __restrict__ h,
                                                  __half* __restrict__ aggp,
                                                  const void* ei) {
    int e = blockIdx.x * 8 + (threadIdx.x >> 5);
    if (e >= NE) return;
    int lane = threadIdx.x & 31;
    int is64 = g_is64;
    long long s = idx_at(ei, e, is64);
    long long d = idx_at(ei, (long long)NE + e, is64);
    uint4 v = *(const uint4*)(h + (size_t)s * HIDD + lane * 8);
    __half* dp = aggp + (size_t)d * HIDD + lane * 8;
    asm volatile("red.global.add.noftz.v4.f16x2 [%0], {%1,%2,%3,%4};"
                 :: "l"(dp), "r"(v.x), "r"(v.y), "r"(v.z), "r"(v.w) : "memory");
}

__global__ __launch_bounds__(256) void comb_kernel(const __half* __restrict__ h,
                                                   const void* sp, const void* dp) {
    int t = blockIdx.x * 256 + threadIdx.x;   // NL*32 total
    int l = t >> 5, q = t & 31;
    int is64 = g_is64;
    long long si = idx_at(sp, l, is64);
    long long di = idx_at(dp, l, is64);
    uint4 s4 = *(const uint4*)(h + (size_t)si * HIDD + q * 8);
    uint4 d4 = *(const uint4*)(h + (size_t)di * HIDD + q * 8);
    uint4 m4, a4;
    const __half2* s2 = (const __half2*)&s4;
    const __half2* d2 = (const __half2*)&d4;
    __half2* m2 = (__half2*)&m4;
    __half2* a2 = (__half2*)&a4;
#pragma unroll
    for (int k = 0; k < 4; k++) {
        m2[k] = __hmul2(s2[k], d2[k]);
        a2[k] = __habs2(__hsub2(s2[k], d2[k]));
    }
    __half* row = g_comb + (size_t)l * 1024;
    *(uint4*)(row + q * 8)       = s4;
    *(uint4*)(row + 256 + q * 8) = d4;
    *(uint4*)(row + 512 + q * 8) = m4;
    *(uint4*)(row + 768 + q * 8) = a4;
}

__global__ void linkfin_kernel(const float* __restrict__ bp2, float* __restrict__ out) {
    int i = blockIdx.x * 256 + threadIdx.x;
    if (i < NL) out[i] = 1.f / (1.f + expf(-(g_lacc[i] + bp2[0])));
}

// ---------------- pipelined fp16 GEMM, BM=64 BN=256, 2 CTAs/SM ------------------
// MODE 0: embed (A = x fp32, convert path)
// MODE 1: sage  (A: mean=(h+agg)*invd conv path for c<4, h async for c>=4)
// MODE 2: link  (A async from comb)

#define SA_    0
#define SW_    8192
#define BUFSZ  40960          // A 8K + W 32K
#define S_MISC 81920
#define SMEMB  (S_MISC + 512 + 1024)

template <int MODE>
__global__ __launch_bounds__(256, 2) void gemm_tc(
    const float* __restrict__ Af, const __half* __restrict__ Ah,
    const __half* __restrict__ Aagg,
    const __half* __restrict__ W1, const __half* __restrict__ W2,
    const float* __restrict__ bias, const float* __restrict__ wp2,
    __half* __restrict__ outp)
{
    extern __shared__ char smraw[];
    char* smc = (char*)(((uintptr_t)smraw + 1023) & ~(uintptr_t)1023);
    const uint32_t sbase = smem_u32(smc);
    const int tid = threadIdx.x;
    const int wid = tid >> 5, l = tid & 31;
    const int wm = wid >> 2, wn = wid & 3;       // 2 x 4 warp grid
    const int row0 = blockIdx.x * 64;

    constexpr int NCH = (MODE == 0) ? 2 : (MODE == 1) ? 8 : 16;
    constexpr int KA  = (MODE == 0) ? FEATD : (MODE == 1) ? HIDD : 1024;

    float* invd_s = (float*)(smc + S_MISC);
    if (MODE == 1 && tid < 64) {
        int row = row0 + tid;
        invd_s[tid] = (row < NN) ? 1.f / (g_deg[row] + 1.f) : 0.f;
    }
    if (MODE == 1) __syncthreads();

    float acc[2][8][4];
#pragma unroll
    for (int mt = 0; mt < 2; mt++)
#pragma unroll
        for (int nt = 0; nt < 8; nt++)
#pragma unroll
            for (int j = 0; j < 4; j++) acc[mt][nt][j] = 0.f;

    float4 phv[2];            // MODE 0 prefetch
    uint4  pqh, pqa;          // MODE 1 mean-path prefetch

    auto needs_conv = [&](int c) { return MODE == 0 || (MODE == 1 && c < 4); };

    auto issueW = [&](int c, int b) {
        const __half* W = (MODE == 1 && c >= 4) ? W2 : W1;
        const int colbase = (MODE == 1) ? ((c & 3) * 64) : (c * 64);
#pragma unroll
        for (int j = 0; j < 8; j++) {            // 2048 uint4 slots
            const int id  = j * 256 + tid;
            const int r   = id >> 3, c16 = id & 7;
            cp16(sbase + b * BUFSZ + SW_ + swz(r * 128 + c16 * 16),
                 W + (size_t)r * KA + colbase + c16 * 8);
        }
    };
    // async A (MODE 1 c>=4 from h; MODE 2 from comb): 512 uint4 slots
    auto issueA = [&](int c, int b) {
        const int colbase = (MODE == 1) ? ((c & 3) * 64) : (c * 64);
#pragma unroll
        for (int j = 0; j < 2; j++) {
            const int id  = j * 256 + tid;
            const int r   = id >> 3, c16 = id & 7;
            const uint32_t dst = sbase + b * BUFSZ + SA_ + swz(r * 128 + c16 * 16);
            if (MODE == 2 || row0 + r < NN)
                cp16(dst, Ah + (size_t)(row0 + r) * KA + colbase + c16 * 8);
            else
                *(uint4*)(smc + (dst - sbase)) = make_uint4(0u, 0u, 0u, 0u);
        }
    };
    auto loadA = [&](int c, int h) {
        const int colbase = (MODE == 1) ? ((c & 3) * 64) : (c * 64);
        if (MODE == 0) {
#pragma unroll
            for (int i = 0; i < 2; i++) {        // 1024 float4 slots over 2 halves
                const int id = (h * 2 + i) * 256 + tid;
                const int r  = id >> 4, c4 = id & 15;
                phv[i] = make_float4(0.f, 0.f, 0.f, 0.f);
                if (row0 + r < NN)
                    phv[i] = *(const float4*)(Af + (size_t)(row0 + r) * KA + colbase + c4 * 4);
            }
        } else {   // MODE 1 mean path: 512 uint4 slots over 2 halves
            const int id = h * 256 + tid;
            const int r  = id >> 3, c8 = id & 7;
            pqh = make_uint4(0u, 0u, 0u, 0u);
            pqa = make_uint4(0u, 0u, 0u, 0u);
            if (row0 + r < NN) {
                const size_t off = (size_t)(row0 + r) * HIDD + colbase + c8 * 8;
                pqh = *(const uint4*)(Ah + off);
                pqa = *(const uint4*)(Aagg + off);
            }
        }
    };
    auto storeA = [&](int c, int h, int b) {
        if (MODE == 0) {
#pragma unroll
            for (int i = 0; i < 2; i++) {
                const int id = (h * 2 + i) * 256 + tid;
                const int r  = id >> 4, c4 = id & 15;
                uint2 o;
                ((__half2*)&o)[0] = __floats2half2_rn(phv[i].x, phv[i].y);
                ((__half2*)&o)[1] = __floats2half2_rn(phv[i].z, phv[i].w);
                *(uint2*)(smc + b * BUFSZ + SA_ + swz(r * 128 + c4 * 8)) = o;
            }
        } else {
            const int id = h * 256 + tid;
            const int r  = id >> 3, c8 = id & 7;
            const float iv = invd_s[r];
            uint4 o;
            const __half2* ph = (const __half2*)&pqh;
            const __half2* pa = (const __half2*)&pqa;
            __half2* po = (__half2*)&o;
#pragma unroll
            for (int k = 0; k < 4; k++) {
                float2 hf = __half22float2(ph[k]);
                float2 af = __half22float2(pa[k]);
                po[k] = __floats2half2_rn((af.x + hf.x) * iv, (af.y + hf.y) * iv);
            }
            *(uint4*)(smc + b * BUFSZ + SA_ + swz(r * 128 + c8 * 16)) = o;
        }
    };
    auto mma2 = [&](int b, int kk0) {
        const uint32_t ab = sbase + b * BUFSZ;
#pragma unroll
        for (int kk = kk0; kk < kk0 + 2; kk++) {
            const uint32_t kbyte = kk * 32;
            uint32_t ar[2][4];
#pragma unroll
            for (int mt = 0; mt < 2; mt++) {
                uint32_t off = swz((wm * 32 + mt * 16 + (l & 15)) * 128 +
                                   kbyte + ((l >> 4) << 4));
                ldmx4(ar[mt], ab + SA_ + off);
            }
            uint32_t bf[8][2];
#pragma unroll
            for (int ntb = 0; ntb < 4; ntb++) {
                const int nt2 = ntb * 2;
                uint32_t off = swz((wn * 64 + (nt2 + ((l >> 4) & 1)) * 8 + (l & 7)) * 128
                                   + kbyte + (((l >> 3) & 1) << 4));
                uint32_t r[4];
                ldmx4(r, ab + SW_ + off);
                bf[nt2][0] = r[0]; bf[nt2][1] = r[1];
                bf[nt2 + 1][0] = r[2]; bf[nt2 + 1][1] = r[3];
            }
#pragma unroll
            for (int nt = 0; nt < 8; nt++)
#pragma unroll
                for (int mt = 0; mt < 2; mt++)
                    MMA_F16(acc[mt][nt], ar[mt], bf[nt]);
        }
    };

    // ---- prologue: chunk 0 into buffer 0 ----
    issueW(0, 0);
    if (needs_conv(0)) {
        loadA(0, 0); storeA(0, 0, 0);
        loadA(0, 1); storeA(0, 1, 0);
    } else {
        issueA(0, 0);
    }
    CP_COMMIT();
    CP_WAIT0();
    __syncthreads();

    // ---- pipelined main loop: 1 sync per chunk ----
    for (int c = 0; c < NCH; c++) {
        const int b = c & 1, nb = b ^ 1;
        const bool pf = (c + 1 < NCH);
        bool cv = pf && needs_conv(c + 1);
        if (pf) {
            issueW(c + 1, nb);
            if (cv) loadA(c + 1, 0); else issueA(c + 1, nb);
            CP_COMMIT();
        }
        mma2(b, 0);
        if (cv) { storeA(c + 1, 0, nb); loadA(c + 1, 1); }
        mma2(b, 2);
        if (cv) storeA(c + 1, 1, nb);
        CP_WAIT0();
        __syncthreads();
    }

    // ---- epilogue ----
    if (MODE == 2) {
#pragma unroll
        for (int mt = 0; mt < 2; mt++) {
            int rloc = wm * 32 + mt * 16 + (l >> 2);
            float s0 = 0.f, s1 = 0.f;
#pragma unroll
            for (int nt = 0; nt < 8; nt++) {
                int col = wn * 64 + nt * 8 + (l & 3) * 2;
                float b0 = bias[col], b1 = bias[col + 1];
                float w0 = wp2[col],  w1 = wp2[col + 1];
                s0 += fmaxf(acc[mt][nt][0] + b0, 0.f) * w0
                    + fmaxf(acc[mt][nt][1] + b1, 0.f) * w1;
                s1 += fmaxf(acc[mt][nt][2] + b0, 0.f) * w0
                    + fmaxf(acc[mt][nt][3] + b1, 0.f) * w1;
            }
            atomicAdd(&g_lacc[row0 + rloc], s0);
            atomicAdd(&g_lacc[row0 + rloc + 8], s1);
        }
    } else {
#pragma unroll
        for (int mt = 0; mt < 2; mt++) {
            int r0 = row0 + wm * 32 + mt * 16 + (l >> 2);
#pragma unroll
            for (int nt = 0; nt < 8; nt++) {
                int col = wn * 64 + nt * 8 + (l & 3) * 2;
                float b0 = bias[col], b1 = bias[col + 1];
                float v0 = acc[mt][nt][0] + b0, v1 = acc[mt][nt][1] + b1;
                float v2 = acc[mt][nt][2] + b0, v3 = acc[mt][nt][3] + b1;
                if (MODE == 1) {
                    v0 = fmaxf(v0, 0.f); v1 = fmaxf(v1, 0.f);
                    v2 = fmaxf(v2, 0.f); v3 = fmaxf(v3, 0.f);
                }
                if (r0 < NN)
                    *(__half2*)(outp + (size_t)r0 * HIDD + col) = __floats2half2_rn(v0, v1);
                if (r0 + 8 < NN)
                    *(__half2*)(outp + (size_t)(r0 + 8) * HIDD + col) = __floats2half2_rn(v2, v3);
            }
        }
    }
}

// ---------------- launcher ------------------------------------------------------
extern "C" void kernel_launch(void* const* d_in, const int* in_sizes, int n_in,
                              void* d_out, int out_size) {
    (void)in_sizes; (void)n_in; (void)out_size;
    const float* x     = (const float*)d_in[0];
    const void*  ei    = d_in[1];
    const void*  sidx  = d_in[3];
    const void*  didx  = d_in[4];
    const float* w_emb = (const float*)d_in[5];
    const float* b_emb = (const float*)d_in[6];
    const float* wl0 = (const float*)d_in[8];
    const float* bl0 = (const float*)d_in[9];
    const float* wr0 = (const float*)d_in[10];
    const float* wl1 = (const float*)d_in[13];
    const float* bl1 = (const float*)d_in[14];
    const float* wr1 = (const float*)d_in[15];
    const float* wp1 = (const float*)d_in[18];
    const float* bp1 = (const float*)d_in[19];
    const float* wp2 = (const float*)d_in[20];
    const float* bp2 = (const float*)d_in[21];
    float* out = (float*)d_out;

    cudaFuncSetAttribute(gemm_tc<0>, cudaFuncAttributeMaxDynamicSharedMemorySize, SMEMB);
    cudaFuncSetAttribute(gemm_tc<1>, cudaFuncAttributeMaxDynamicSharedMemorySize, SMEMB);
    cudaFuncSetAttribute(gemm_tc<2>, cudaFuncAttributeMaxDynamicSharedMemorySize, SMEMB);

    __half *wembC, *wl0C, *wr0C, *wl1C, *wr1C, *wp1C;
    __half *hbuf, *aggbuf, *agg2buf, *h2buf, *combbuf;
    cudaGetSymbolAddress((void**)&wembC, g_wembC);
    cudaGetSymbolAddress((void**)&wl0C, g_wl0C);
    cudaGetSymbolAddress((void**)&wr0C, g_wr0C);
    cudaGetSymbolAddress((void**)&wl1C, g_wl1C);
    cudaGetSymbolAddress((void**)&wr1C, g_wr1C);
    cudaGetSymbolAddress((void**)&wp1C, g_wp1C);
    cudaGetSymbolAddress((void**)&hbuf, g_h);
    cudaGetSymbolAddress((void**)&aggbuf, g_agg);
    cudaGetSymbolAddress((void**)&agg2buf, g_agg2);
    cudaGetSymbolAddress((void**)&h2buf, g_h2);
    cudaGetSymbolAddress((void**)&combbuf, g_comb);

    const int pgrid = (NN * HIDD / 8 + 255) / 256;   // covers zeroing + conversions
    const int ggrid = (NN + 63) / 64;                // 1563
    const int lgrid = NL / 64;                       // 256

    prep_kernel<<<pgrid, 256>>>(ei, w_emb, wl0, wr0, wl1, wr1, wp1);                // 0
    deg_kernel<<<(NE + 255) / 256, 256>>>(ei);                                      // 1
    gemm_tc<0><<<ggrid, 256, SMEMB>>>(x, nullptr, nullptr, wembC, nullptr,
                                      b_emb, nullptr, hbuf);                        // 2
    agg_kernel<<<NE / 8, 256>>>(hbuf, aggbuf, ei);                                  // 3
    gemm_tc<1><<<ggrid, 256, SMEMB>>>(nullptr, hbuf, aggbuf, wl0C, wr0C,
                                      bl0, nullptr, h2buf);                         // 4
    agg_kernel<<<NE / 8, 256>>>(h2buf, agg2buf, ei);                                // 5 <- ncu
    gemm_tc<1><<<ggrid, 256, SMEMB>>>(nullptr, h2buf, agg2buf, wl1C, wr1C,
                                      bl1, nullptr, hbuf);                          // 6
    comb_kernel<<<NL * 32 / 256, 256>>>(hbuf, sidx, didx);                          // 7
    gemm_tc<2><<<lgrid, 256, SMEMB>>>(nullptr, combbuf, nullptr, wp1C, nullptr,
                                      bp1, wp2, nullptr);                           // 8
    linkfin_kernel<<<NL / 256, 256>>>(bp2, out);                                    // 9
}